// round 12
// baseline (speedup 1.0000x reference)
#include <cuda_runtime.h>
#include <cuda_fp16.h>
#include <math.h>

#define Nn 100000
#define Cc 256
#define Hh 8
#define Dd 32
#define SEMd 128
#define EMAX 700000
#define NEG_SLOPE 0.2f
#define TILE 4096
#define NB 25   // ceil(Nn / TILE)
#define SMEM_FUSED (64 * 264 * 2 + 128 * 72 * 2 + 128 * 4 + 128 * 4 + 256 * 4)

// ---------------- scratch (static device memory; no allocs) ----------------
__device__ __half g_h16[Nn * Dd];        // [N,32] f16 (consumed only by gat phase)
__device__ float g_s[Nn * 32];           // [N,32]: 0-7 l1.dst, 8-15 l1.src, 16-23 l2.dst, 24-31 l2.src
__device__ __half g_Z16[2ull * Nn * Cc]; // f16 Z1,Z2 (only copy of Z; read by k_comb)
__device__ __half g_fcw16[SEMd * Cc];
__device__ float g_Aall[32 * 32];
__device__ int   g_deg[2 * Nn];
__device__ int   g_cur[2 * Nn];
__device__ int   g_rowptr[2 * (Nn + 1)];
__device__ int   g_csr[2 * EMAX];
__device__ int   g_bsum[2 * NB];
__device__ float g_t[2];

// ---------------- helpers ----------------
__device__ __forceinline__ float tanh_apx(float x) {
    float r; asm("tanh.approx.f32 %0, %1;" : "=f"(r) : "f"(x)); return r;
}
__device__ __forceinline__ unsigned smem_u32(const void* p) {
    return (unsigned)__cvta_generic_to_shared(p);
}
#define LDSM4(r0, r1, r2, r3, addr) \
    asm volatile("ldmatrix.sync.aligned.m8n8.x4.shared.b16 {%0,%1,%2,%3}, [%4];" \
                 : "=r"(r0), "=r"(r1), "=r"(r2), "=r"(r3) : "r"(addr))
#define MMA16816(c, a0, a1, a2, a3, b0, b1) \
    asm volatile("mma.sync.aligned.m16n8k16.row.col.f32.f16.f16.f32 " \
                 "{%0,%1,%2,%3}, {%4,%5,%6,%7}, {%8,%9}, {%0,%1,%2,%3};" \
                 : "+f"(c[0]), "+f"(c[1]), "+f"(c[2]), "+f"(c[3]) \
                 : "r"(a0), "r"(a1), "r"(a2), "r"(a3), "r"(b0), "r"(b1))
#define FMA2(d, a, b) asm("fma.rn.f32x2 %0, %1, %2, %0;" : "+l"(d) : "l"(a), "l"(b))
#define PACK2(out, lo, hi) asm("mov.b64 %0, {%1, %2};" : "=l"(out) : "f"(lo), "f"(hi))
#define UNPACK2(lo, hi, in) asm("mov.b64 {%0, %1}, %2;" : "=f"(lo), "=f"(hi) : "l"(in))

// ---------------- setup: zero deg/t + A_all + fcw16 ----------------
__global__ __launch_bounds__(1024) void k_setup(const float* __restrict__ att1,
                                                const float* __restrict__ att2,
                                                const float* __restrict__ fcw) {
    int i = blockIdx.x * blockDim.x + threadIdx.x;
    if (i < 2 * Nn) g_deg[i] = 0;
    if (i < SEMd * Cc) g_fcw16[i] = __float2half_rn(fcw[i]);
    if (i < 1024) {
        int j = i >> 5, k = i & 31;
        float v;
        if (j < 8)       v = att1[j * 64 + k];
        else if (j < 16) v = att1[(j - 8) * 64 + 32 + k];
        else if (j < 24) v = att2[(j - 16) * 64 + k];
        else             v = att2[(j - 24) * 64 + 32 + k];
        g_Aall[j * 32 + k] = v;
    }
    if (i < 2) g_t[i] = 0.f;
}

// ---------------- h = x @ W^T and s = h @ A_all^T, fused, f32x2, pipelined --
__global__ __launch_bounds__(128) void k_hs(const float* __restrict__ x,
                                            const float* __restrict__ W) {
    __shared__ float xsT[32][134];
    __shared__ float wsT[32][36];
    const int tid = threadIdx.x;
    const int jl = tid & 7;
    const int g  = tid >> 3;
    const int n0 = blockIdx.x * 128;

    unsigned long long acc[4][4];
#pragma unroll
    for (int p = 0; p < 4; p++)
#pragma unroll
        for (int j = 0; j < 4; j++) acc[p][j] = 0ull;

    float4 xreg[8];
    float4 wreg[2];

#pragma unroll
    for (int it = 0; it < 8; it++) {
        int idx = tid + it * 128;
        int r = idx >> 3, c4 = (idx & 7) * 4;
        int n = n0 + r;
        xreg[it] = (n < Nn) ? *(const float4*)&x[n * Cc + c4]
                            : make_float4(0.f, 0.f, 0.f, 0.f);
    }
#pragma unroll
    for (int it = 0; it < 2; it++) {
        int idx = tid + it * 128;
        int r = idx >> 3, c4 = (idx & 7) * 4;
        wreg[it] = *(const float4*)&W[r * Cc + c4];
    }
#pragma unroll
    for (int it = 0; it < 8; it++) {
        int idx = tid + it * 128;
        int r = idx >> 3, c4 = (idx & 7) * 4;
        xsT[c4 + 0][r] = xreg[it].x;
        xsT[c4 + 1][r] = xreg[it].y;
        xsT[c4 + 2][r] = xreg[it].z;
        xsT[c4 + 3][r] = xreg[it].w;
    }
#pragma unroll
    for (int it = 0; it < 2; it++) {
        int idx = tid + it * 128;
        int r = idx >> 3, c4 = (idx & 7) * 4;
        wsT[c4 + 0][r] = wreg[it].x;
        wsT[c4 + 1][r] = wreg[it].y;
        wsT[c4 + 2][r] = wreg[it].z;
        wsT[c4 + 3][r] = wreg[it].w;
    }

    for (int t = 0; t < 8; t++) {
        if (t < 7) {
            int c0n = (t + 1) * 32;
#pragma unroll
            for (int it = 0; it < 8; it++) {
                int idx = tid + it * 128;
                int r = idx >> 3, c4 = (idx & 7) * 4;
                int n = n0 + r;
                xreg[it] = (n < Nn) ? *(const float4*)&x[n * Cc + c0n + c4]
                                    : make_float4(0.f, 0.f, 0.f, 0.f);
            }
#pragma unroll
            for (int it = 0; it < 2; it++) {
                int idx = tid + it * 128;
                int r = idx >> 3, c4 = (idx & 7) * 4;
                wreg[it] = *(const float4*)&W[r * Cc + c0n + c4];
            }
        }
        __syncthreads();
#pragma unroll
        for (int kk = 0; kk < 32; kk++) {
            float4 wv = *(const float4*)&wsT[kk][jl * 4];
            unsigned long long wp[4];
            PACK2(wp[0], wv.x, wv.x);
            PACK2(wp[1], wv.y, wv.y);
            PACK2(wp[2], wv.z, wv.z);
            PACK2(wp[3], wv.w, wv.w);
#pragma unroll
            for (int p = 0; p < 4; p++) {
                unsigned long long zp = *(const unsigned long long*)&xsT[kk][g * 8 + 2 * p];
#pragma unroll
                for (int j = 0; j < 4; j++) FMA2(acc[p][j], zp, wp[j]);
            }
        }
        __syncthreads();
        if (t < 7) {
#pragma unroll
            for (int it = 0; it < 8; it++) {
                int idx = tid + it * 128;
                int r = idx >> 3, c4 = (idx & 7) * 4;
                xsT[c4 + 0][r] = xreg[it].x;
                xsT[c4 + 1][r] = xreg[it].y;
                xsT[c4 + 2][r] = xreg[it].z;
                xsT[c4 + 3][r] = xreg[it].w;
            }
#pragma unroll
            for (int it = 0; it < 2; it++) {
                int idx = tid + it * 128;
                int r = idx >> 3, c4 = (idx & 7) * 4;
                wsT[c4 + 0][r] = wreg[it].x;
                wsT[c4 + 1][r] = wreg[it].y;
                wsT[c4 + 2][r] = wreg[it].z;
                wsT[c4 + 3][r] = wreg[it].w;
            }
        }
    }
    // h epilogue: f16 STG + scatter h^T into xsT
#pragma unroll
    for (int p = 0; p < 4; p++) {
        float lo[4], hi[4];
#pragma unroll
        for (int j = 0; j < 4; j++) UNPACK2(lo[j], hi[j], acc[p][j]);
        int r = g * 8 + 2 * p;
        int n = n0 + r;
#pragma unroll
        for (int j = 0; j < 4; j++) { xsT[jl * 4 + j][r] = lo[j]; xsT[jl * 4 + j][r + 1] = hi[j]; }
        if (n < Nn) {
            union { __half2 h2[2]; uint2 u; } pk;
            pk.h2[0] = __floats2half2_rn(lo[0], lo[1]);
            pk.h2[1] = __floats2half2_rn(lo[2], lo[3]);
            *(uint2*)&g_h16[n * Dd + jl * 4] = pk.u;
        }
        if (n + 1 < Nn) {
            union { __half2 h2[2]; uint2 u; } pk;
            pk.h2[0] = __floats2half2_rn(hi[0], hi[1]);
            pk.h2[1] = __floats2half2_rn(hi[2], hi[3]);
            *(uint2*)&g_h16[(n + 1) * Dd + jl * 4] = pk.u;
        }
    }
#pragma unroll
    for (int it = 0; it < 2; it++) {
        int idx = tid + it * 128;
        int r = idx >> 3, c4 = (idx & 7) * 4;
        float4 v = *(const float4*)&g_Aall[r * 32 + c4];
        wsT[c4 + 0][r] = v.x;
        wsT[c4 + 1][r] = v.y;
        wsT[c4 + 2][r] = v.z;
        wsT[c4 + 3][r] = v.w;
    }
    __syncthreads();
    unsigned long long sacc[4][4];
#pragma unroll
    for (int p = 0; p < 4; p++)
#pragma unroll
        for (int j = 0; j < 4; j++) sacc[p][j] = 0ull;
#pragma unroll
    for (int kk = 0; kk < 32; kk++) {
        float4 wv = *(const float4*)&wsT[kk][jl * 4];
        unsigned long long wp[4];
        PACK2(wp[0], wv.x, wv.x);
        PACK2(wp[1], wv.y, wv.y);
        PACK2(wp[2], wv.z, wv.z);
        PACK2(wp[3], wv.w, wv.w);
#pragma unroll
        for (int p = 0; p < 4; p++) {
            unsigned long long zp = *(const unsigned long long*)&xsT[kk][g * 8 + 2 * p];
#pragma unroll
            for (int j = 0; j < 4; j++) FMA2(sacc[p][j], zp, wp[j]);
        }
    }
#pragma unroll
    for (int p = 0; p < 4; p++) {
        float lo[4], hi[4];
#pragma unroll
        for (int j = 0; j < 4; j++) UNPACK2(lo[j], hi[j], sacc[p][j]);
        int n = n0 + g * 8 + 2 * p;
        if (n < Nn) *(float4*)&g_s[n * 32 + jl * 4] = make_float4(lo[0], lo[1], lo[2], lo[3]);
        if (n + 1 < Nn) *(float4*)&g_s[(n + 1) * 32 + jl * 4] = make_float4(hi[0], hi[1], hi[2], hi[3]);
    }
}

// ---------------- CSR build ----------------
__global__ void k_hist(const int* __restrict__ ei1, int E1,
                       const int* __restrict__ ei2, int E2) {
    int e = blockIdx.x * blockDim.x + threadIdx.x;
    if (e < E1) atomicAdd(&g_deg[ei1[E1 + e]], 1);
    if (e < E2) atomicAdd(&g_deg[Nn + ei2[E2 + e]], 1);
}

__global__ __launch_bounds__(1024) void k_scan1() {
    const int set = blockIdx.y;
    const int blk = blockIdx.x;
    const int t = threadIdx.x;
    const int lane = t & 31, wid = t >> 5;
    __shared__ int wsum[32];
    const int* deg = &g_deg[set * Nn];
    int* rp = &g_rowptr[set * (Nn + 1)];
    int base = blk * TILE + t * 4;

    int4 v = make_int4(0, 0, 0, 0);
    if (base + 3 < Nn) v = *(const int4*)&deg[base];
    else {
        if (base + 0 < Nn) v.x = deg[base + 0];
        if (base + 1 < Nn) v.y = deg[base + 1];
        if (base + 2 < Nn) v.z = deg[base + 2];
        if (base + 3 < Nn) v.w = deg[base + 3];
    }
    int tsum = v.x + v.y + v.z + v.w;
    int incl = tsum;
#pragma unroll
    for (int off = 1; off < 32; off <<= 1) {
        int nv = __shfl_up_sync(0xffffffffu, incl, off);
        if (lane >= off) incl += nv;
    }
    if (lane == 31) wsum[wid] = incl;
    __syncthreads();
    if (wid == 0) {
        int w = wsum[lane];
        int wi = w;
#pragma unroll
        for (int off = 1; off < 32; off <<= 1) {
            int nv = __shfl_up_sync(0xffffffffu, wi, off);
            if (lane >= off) wi += nv;
        }
        wsum[lane] = wi - w;
        if (lane == 31) g_bsum[set * NB + blk] = wi;
    }
    __syncthreads();
    int off0 = wsum[wid] + incl - tsum;
    if (base < Nn) {
        int o = off0;
        rp[base] = o; o += v.x;
        if (base + 1 < Nn) rp[base + 1] = o; o += v.y;
        if (base + 2 < Nn) rp[base + 2] = o; o += v.z;
        if (base + 3 < Nn) rp[base + 3] = o;
    }
}

__global__ __launch_bounds__(256) void k_scan3(int E1, int E2) {
    __shared__ int boff[2 * 32];
    int t = threadIdx.x;
    if (t < 64) {
        int set = t >> 5, lane = t & 31;
        int v = (lane < NB) ? g_bsum[set * NB + lane] : 0;
        int incl = v;
#pragma unroll
        for (int off = 1; off < 32; off <<= 1) {
            int nv = __shfl_up_sync(0xffffffffu, incl, off);
            if (lane >= off) incl += nv;
        }
        boff[set * 32 + lane] = incl - v;
    }
    __syncthreads();
    int i = blockIdx.x * blockDim.x + t;
    if (i < 2 * Nn) {
        int set = (i >= Nn) ? 1 : 0;
        int loc = i - set * Nn;
        int vabs = g_rowptr[set * (Nn + 1) + loc] + boff[set * 32 + loc / TILE];
        g_rowptr[set * (Nn + 1) + loc] = vabs;
        g_cur[i] = vabs;
    }
    if (i == 0) {
        g_rowptr[Nn] = E1;
        g_rowptr[(Nn + 1) + Nn] = E2;
    }
}

__global__ void k_scatter(const int* __restrict__ ei1, int E1,
                          const int* __restrict__ ei2, int E2) {
    int e = blockIdx.x * blockDim.x + threadIdx.x;
    if (e < E1) {
        int src = ei1[e], dst = ei1[E1 + e];
        int pos = atomicAdd(&g_cur[dst], 1);
        g_csr[pos] = src;
    }
    if (e < E2) {
        int src = ei2[e], dst = ei2[E2 + e];
        int pos = atomicAdd(&g_cur[Nn + dst], 1);
        g_csr[EMAX + pos] = src;
    }
}

// ---------------- fused GAT + semantic score (one layer per blockIdx.y) -----
// Phase 1: 8 warps x 8 nodes -> Z tile in smem Ash[64][264] (+gmem for comb)
// Phase 2: mma score GEMM with A resident, B staged per 64-K chunk
__global__ __launch_bounds__(256) void k_gatscore(const float* __restrict__ fcb,
                                                  const float* __restrict__ q) {
    extern __shared__ char dsm[];
    __half (*Ash)[264] = (__half(*)[264])dsm;                        // 33792 B
    __half (*Bsh)[72]  = (__half(*)[72])(dsm + 64 * 264 * 2);        // 18432 B
    float* sb  = (float*)(dsm + 64 * 264 * 2 + 128 * 72 * 2);
    float* sq  = sb + 128;
    float* red = sq + 128;

    const int set = blockIdx.y;
    const int tid = threadIdx.x;
    const int lane = tid & 31, wid = tid >> 5;
    const int n0 = blockIdx.x * 64;

    if (tid < 128) { sb[tid] = fcb[tid]; sq[tid] = q[tid]; }

    // ---- phase 1: GAT for 64 nodes ----
    {
        __half* Z16 = &g_Z16[(size_t)set * Nn * Cc];
        const int offd = set * 16, offs = set * 16 + 8;
        const int* csr = &g_csr[set * EMAX];
        const int head = lane >> 2;
        const int dpart = (lane & 3) * 8;
        const bool sc_lane = (lane < 8);
#pragma unroll 1
        for (int ii = 0; ii < 8; ii++) {
            int ln = wid * 8 + ii;
            int node = n0 + ln;
            if (node < Nn) {
                const int beg = g_rowptr[set * (Nn + 1) + node];
                const int end = g_rowptr[set * (Nn + 1) + node + 1];
                float sd = sc_lane ? g_s[node * 32 + offd + lane] : 0.f;
                float lsum = 0.f;
                unsigned long long acc[4];
#pragma unroll
                for (int i = 0; i < 4; i++) acc[i] = 0ull;
                for (int e = beg; e < end; e++) {
                    int src = csr[e];
                    float p = 0.f;
                    if (sc_lane) {
                        float sc = sd + g_s[src * 32 + offs + lane];
                        sc = sc > 0.f ? sc : NEG_SLOPE * sc;
                        p = __expf(sc);
                        lsum += p;
                    }
                    float ph = __shfl_sync(0xffffffffu, p, head);
                    uint4 hv = *(const uint4*)&g_h16[src * Dd + dpart];
                    const __half2* h2 = (const __half2*)&hv;
                    unsigned long long pp;
                    PACK2(pp, ph, ph);
#pragma unroll
                    for (int i = 0; i < 4; i++) {
                        float2 f = __half22float2(h2[i]);
                        unsigned long long hp;
                        PACK2(hp, f.x, f.y);
                        FMA2(acc[i], hp, pp);
                    }
                }
                float ls = __shfl_sync(0xffffffffu, lsum, head);
                float inv = 1.0f / ls;
                union { __half2 h2[4]; uint4 u; } outp;
#pragma unroll
                for (int i = 0; i < 4; i++) {
                    float lo, hi;
                    UNPACK2(lo, hi, acc[i]);
                    lo *= inv; hi *= inv;
                    lo = lo > 0.f ? lo : expm1f(lo);
                    hi = hi > 0.f ? hi : expm1f(hi);
                    outp.h2[i] = __floats2half2_rn(lo, hi);
                }
                // head*Dd + dpart == lane*8
                *(uint4*)&Ash[ln][lane * 8] = outp.u;
                *(uint4*)&Z16[node * Cc + lane * 8] = outp.u;
            } else {
                *(uint4*)&Ash[ln][lane * 8] = make_uint4(0, 0, 0, 0);
            }
        }
    }
    __syncthreads();

    // ---- phase 2: score GEMM, A resident in Ash ----
    const int wm = wid & 3, wn = wid >> 2;
    const int mt = lane >> 3, rr = lane & 7;
    float c[8][4];
#pragma unroll
    for (int nt = 0; nt < 8; nt++)
#pragma unroll
        for (int i = 0; i < 4; i++) c[nt][i] = 0.f;

    for (int k0 = 0; k0 < Cc; k0 += 64) {
#pragma unroll
        for (int it = 0; it < 4; it++) {
            int idx = tid + it * 256;
            int row = idx >> 3, c8 = idx & 7;
            *(int4*)&Bsh[row][c8 * 8] = *(const int4*)&g_fcw16[row * Cc + k0 + c8 * 8];
        }
        __syncthreads();
#pragma unroll
        for (int ks = 0; ks < 4; ks++) {
            const int kk = ks * 16;
            unsigned a0, a1, a2, a3;
            {
                unsigned addr = smem_u32(&Ash[wm * 16 + ((mt & 1) << 3) + rr][k0 + kk + ((mt >> 1) << 3)]);
                LDSM4(a0, a1, a2, a3, addr);
            }
#pragma unroll
            for (int pb = 0; pb < 4; pb++) {
                unsigned b0, b1, b2, b3;
                unsigned addr = smem_u32(&Bsh[wn * 64 + pb * 16 + ((mt >> 1) << 3) + rr][kk + ((mt & 1) << 3)]);
                LDSM4(b0, b1, b2, b3, addr);
                MMA16816(c[2 * pb],     a0, a1, a2, a3, b0, b1);
                MMA16816(c[2 * pb + 1], a0, a1, a2, a3, b2, b3);
            }
        }
        __syncthreads();
    }

    float psum = 0.f;
    const int rbase = lane >> 2, cb = (lane & 3) * 2;
#pragma unroll
    for (int nt = 0; nt < 8; nt++) {
#pragma unroll
        for (int i = 0; i < 4; i++) {
            int m = wm * 16 + rbase + ((i >> 1) << 3);
            int j = wn * 64 + nt * 8 + cb + (i & 1);
            if (n0 + m < Nn) psum += tanh_apx(c[nt][i] + sb[j]) * sq[j];
        }
    }
    red[tid] = psum;
    __syncthreads();
    for (int s = 128; s > 0; s >>= 1) {
        if (tid < s) red[tid] += red[tid + s];
        __syncthreads();
    }
    if (tid == 0) atomicAdd(&g_t[set], red[0]);
}

// ---------------- out = V0*Z1 + V1*Z2 (softmax inline; f16 in, f32 out) -----
__global__ __launch_bounds__(256) void k_comb(float* __restrict__ out) {
    int i = blockIdx.x * blockDim.x + threadIdx.x;
    const int total8 = Nn * Cc / 8;
    if (i >= total8) return;
    float s0 = g_t[0] * (1.0f / (float)Nn);
    float s1 = g_t[1] * (1.0f / (float)Nn);
    float mm = fmaxf(s0, s1);
    float e0 = __expf(s0 - mm), e1 = __expf(s1 - mm);
    float inv = 1.0f / (e0 + e1);
    float v0 = e0 * inv, v1 = e1 * inv;
    uint4 ra = *(const uint4*)&g_Z16[(size_t)i * 8];
    uint4 rb = *(const uint4*)&g_Z16[(size_t)Nn * Cc + (size_t)i * 8];
    const __half2* ha = (const __half2*)&ra;
    const __half2* hb = (const __half2*)&rb;
    float4 o0, o1;
    float2 a, b;
    a = __half22float2(ha[0]); b = __half22float2(hb[0]);
    o0.x = v0 * a.x + v1 * b.x; o0.y = v0 * a.y + v1 * b.y;
    a = __half22float2(ha[1]); b = __half22float2(hb[1]);
    o0.z = v0 * a.x + v1 * b.x; o0.w = v0 * a.y + v1 * b.y;
    a = __half22float2(ha[2]); b = __half22float2(hb[2]);
    o1.x = v0 * a.x + v1 * b.x; o1.y = v0 * a.y + v1 * b.y;
    a = __half22float2(ha[3]); b = __half22float2(hb[3]);
    o1.z = v0 * a.x + v1 * b.x; o1.w = v0 * a.y + v1 * b.y;
    *(float4*)&out[(size_t)i * 8] = o0;
    *(float4*)&out[(size_t)i * 8 + 4] = o1;
}

// ---------------- launch (multi-stream fork/join, capture-safe) -------------
extern "C" void kernel_launch(void* const* d_in, const int* in_sizes, int n_in,
                              void* d_out, int out_size) {
    const float* x    = (const float*)d_in[0];
    const float* W    = (const float*)d_in[1];
    const float* att1 = (const float*)d_in[2];
    const float* att2 = (const float*)d_in[3];
    const float* fcw  = (const float*)d_in[4];
    const float* fcb  = (const float*)d_in[5];
    const float* q    = (const float*)d_in[6];
    const int*   ei1  = (const int*)d_in[7];
    const int*   ei2  = (const int*)d_in[8];
    const int E1 = in_sizes[7] / 2;
    const int E2 = in_sizes[8] / 2;
    const int Emax = (E1 > E2) ? E1 : E2;
    float* out = (float*)d_out;

    static cudaStream_t s1 = 0;
    static cudaEvent_t evSetup = 0, evCsr = 0;
    if (!s1) {
        cudaStreamCreateWithFlags(&s1, cudaStreamNonBlocking);
        cudaEventCreateWithFlags(&evSetup, cudaEventDisableTiming);
        cudaEventCreateWithFlags(&evCsr, cudaEventDisableTiming);
        cudaFuncSetAttribute(k_gatscore, cudaFuncAttributeMaxDynamicSharedMemorySize, SMEM_FUSED);
    }

    // main stream: setup, then fork
    k_setup<<<(2 * Nn + 1023) / 1024, 1024>>>(att1, att2, fcw);
    cudaEventRecord(evSetup, 0);

    // side stream: CSR build chain (independent of k_hs)
    cudaStreamWaitEvent(s1, evSetup, 0);
    k_hist<<<(Emax + 255) / 256, 256, 0, s1>>>(ei1, E1, ei2, E2);
    k_scan1<<<dim3(NB, 2), 1024, 0, s1>>>();
    k_scan3<<<(2 * Nn + 255) / 256, 256, 0, s1>>>(E1, E2);
    k_scatter<<<(Emax + 255) / 256, 256, 0, s1>>>(ei1, E1, ei2, E2);
    cudaEventRecord(evCsr, s1);

    // main stream: the h/s GEMM (overlaps the CSR chain)
    k_hs<<<(Nn + 127) / 128, 128>>>(x, W);

    // join, then fused gat+score for both layers in one launch
    cudaStreamWaitEvent(0, evCsr, 0);
    k_gatscore<<<dim3((Nn + 63) / 64, 2), 256, SMEM_FUSED>>>(fcb, q);

    // final combine (softmax inline)
    k_comb<<<(Nn * Cc / 8 + 255) / 256, 256>>>(out);
}

// round 13
// speedup vs baseline: 1.1038x; 1.1038x over previous
#include <cuda_runtime.h>
#include <cuda_fp16.h>
#include <math.h>

#define Nn 100000
#define Cc 256
#define Hh 8
#define Dd 32
#define SEMd 128
#define EMAX 700000
#define NEG_SLOPE 0.2f
#define TILE 4096
#define NB 25   // ceil(Nn / TILE)

// ---------------- scratch (static device memory; no allocs) ----------------
__device__ __half g_h16[Nn * Dd];        // [N,32] f16 (consumed only by k_gat)
__device__ float g_s[Nn * 32];           // [N,32]: 0-7 l1.dst, 8-15 l1.src, 16-23 l2.dst, 24-31 l2.src
__device__ __half g_Z16[2ull * Nn * Cc]; // f16 Z1,Z2 (only copy of Z)
__device__ __half g_fcw16[SEMd * Cc];
__device__ float g_Aall[32 * 32];
__device__ int   g_deg[2 * Nn];
__device__ int   g_cur[2 * Nn];
__device__ int   g_rowptr[2 * (Nn + 1)];
__device__ int   g_csr[2 * EMAX];
__device__ int   g_bsum[2 * NB];
__device__ float g_t[2];

// ---------------- helpers ----------------
__device__ __forceinline__ float tanh_apx(float x) {
    float r; asm("tanh.approx.f32 %0, %1;" : "=f"(r) : "f"(x)); return r;
}
__device__ __forceinline__ unsigned smem_u32(const void* p) {
    return (unsigned)__cvta_generic_to_shared(p);
}
#define LDSM4(r0, r1, r2, r3, addr) \
    asm volatile("ldmatrix.sync.aligned.m8n8.x4.shared.b16 {%0,%1,%2,%3}, [%4];" \
                 : "=r"(r0), "=r"(r1), "=r"(r2), "=r"(r3) : "r"(addr))
#define MMA16816(c, a0, a1, a2, a3, b0, b1) \
    asm volatile("mma.sync.aligned.m16n8k16.row.col.f32.f16.f16.f32 " \
                 "{%0,%1,%2,%3}, {%4,%5,%6,%7}, {%8,%9}, {%0,%1,%2,%3};" \
                 : "+f"(c[0]), "+f"(c[1]), "+f"(c[2]), "+f"(c[3]) \
                 : "r"(a0), "r"(a1), "r"(a2), "r"(a3), "r"(b0), "r"(b1))
#define FMA2(d, a, b) asm("fma.rn.f32x2 %0, %1, %2, %0;" : "+l"(d) : "l"(a), "l"(b))
#define PACK2(out, lo, hi) asm("mov.b64 %0, {%1, %2};" : "=l"(out) : "f"(lo), "f"(hi))
#define UNPACK2(lo, hi, in) asm("mov.b64 {%0, %1}, %2;" : "=f"(lo), "=f"(hi) : "l"(in))

// ---------------- setup: zero deg/t + A_all + fcw16 ----------------
__global__ __launch_bounds__(1024) void k_setup(const float* __restrict__ att1,
                                                const float* __restrict__ att2,
                                                const float* __restrict__ fcw) {
    int i = blockIdx.x * blockDim.x + threadIdx.x;
    if (i < 2 * Nn) g_deg[i] = 0;
    if (i < SEMd * Cc) g_fcw16[i] = __float2half_rn(fcw[i]);
    if (i < 1024) {
        int j = i >> 5, k = i & 31;
        float v;
        if (j < 8)       v = att1[j * 64 + k];
        else if (j < 16) v = att1[(j - 8) * 64 + 32 + k];
        else if (j < 24) v = att2[(j - 16) * 64 + k];
        else             v = att2[(j - 24) * 64 + 32 + k];
        g_Aall[j * 32 + k] = v;
    }
    if (i < 2) g_t[i] = 0.f;
}

// ---------------- h = x @ W^T and s = h @ A_all^T, fused, f32x2, pipelined --
__global__ __launch_bounds__(128) void k_hs(const float* __restrict__ x,
                                            const float* __restrict__ W) {
    __shared__ float xsT[32][134];
    __shared__ float wsT[32][36];
    const int tid = threadIdx.x;
    const int jl = tid & 7;
    const int g  = tid >> 3;
    const int n0 = blockIdx.x * 128;

    unsigned long long acc[4][4];
#pragma unroll
    for (int p = 0; p < 4; p++)
#pragma unroll
        for (int j = 0; j < 4; j++) acc[p][j] = 0ull;

    float4 xreg[8];
    float4 wreg[2];

#pragma unroll
    for (int it = 0; it < 8; it++) {
        int idx = tid + it * 128;
        int r = idx >> 3, c4 = (idx & 7) * 4;
        int n = n0 + r;
        xreg[it] = (n < Nn) ? *(const float4*)&x[n * Cc + c4]
                            : make_float4(0.f, 0.f, 0.f, 0.f);
    }
#pragma unroll
    for (int it = 0; it < 2; it++) {
        int idx = tid + it * 128;
        int r = idx >> 3, c4 = (idx & 7) * 4;
        wreg[it] = *(const float4*)&W[r * Cc + c4];
    }
#pragma unroll
    for (int it = 0; it < 8; it++) {
        int idx = tid + it * 128;
        int r = idx >> 3, c4 = (idx & 7) * 4;
        xsT[c4 + 0][r] = xreg[it].x;
        xsT[c4 + 1][r] = xreg[it].y;
        xsT[c4 + 2][r] = xreg[it].z;
        xsT[c4 + 3][r] = xreg[it].w;
    }
#pragma unroll
    for (int it = 0; it < 2; it++) {
        int idx = tid + it * 128;
        int r = idx >> 3, c4 = (idx & 7) * 4;
        wsT[c4 + 0][r] = wreg[it].x;
        wsT[c4 + 1][r] = wreg[it].y;
        wsT[c4 + 2][r] = wreg[it].z;
        wsT[c4 + 3][r] = wreg[it].w;
    }

    for (int t = 0; t < 8; t++) {
        if (t < 7) {
            int c0n = (t + 1) * 32;
#pragma unroll
            for (int it = 0; it < 8; it++) {
                int idx = tid + it * 128;
                int r = idx >> 3, c4 = (idx & 7) * 4;
                int n = n0 + r;
                xreg[it] = (n < Nn) ? *(const float4*)&x[n * Cc + c0n + c4]
                                    : make_float4(0.f, 0.f, 0.f, 0.f);
            }
#pragma unroll
            for (int it = 0; it < 2; it++) {
                int idx = tid + it * 128;
                int r = idx >> 3, c4 = (idx & 7) * 4;
                wreg[it] = *(const float4*)&W[r * Cc + c0n + c4];
            }
        }
        __syncthreads();
#pragma unroll
        for (int kk = 0; kk < 32; kk++) {
            float4 wv = *(const float4*)&wsT[kk][jl * 4];
            unsigned long long wp[4];
            PACK2(wp[0], wv.x, wv.x);
            PACK2(wp[1], wv.y, wv.y);
            PACK2(wp[2], wv.z, wv.z);
            PACK2(wp[3], wv.w, wv.w);
#pragma unroll
            for (int p = 0; p < 4; p++) {
                unsigned long long zp = *(const unsigned long long*)&xsT[kk][g * 8 + 2 * p];
#pragma unroll
                for (int j = 0; j < 4; j++) FMA2(acc[p][j], zp, wp[j]);
            }
        }
        __syncthreads();
        if (t < 7) {
#pragma unroll
            for (int it = 0; it < 8; it++) {
                int idx = tid + it * 128;
                int r = idx >> 3, c4 = (idx & 7) * 4;
                xsT[c4 + 0][r] = xreg[it].x;
                xsT[c4 + 1][r] = xreg[it].y;
                xsT[c4 + 2][r] = xreg[it].z;
                xsT[c4 + 3][r] = xreg[it].w;
            }
#pragma unroll
            for (int it = 0; it < 2; it++) {
                int idx = tid + it * 128;
                int r = idx >> 3, c4 = (idx & 7) * 4;
                wsT[c4 + 0][r] = wreg[it].x;
                wsT[c4 + 1][r] = wreg[it].y;
                wsT[c4 + 2][r] = wreg[it].z;
                wsT[c4 + 3][r] = wreg[it].w;
            }
        }
    }
    // h epilogue: f16 STG + scatter h^T into xsT
#pragma unroll
    for (int p = 0; p < 4; p++) {
        float lo[4], hi[4];
#pragma unroll
        for (int j = 0; j < 4; j++) UNPACK2(lo[j], hi[j], acc[p][j]);
        int r = g * 8 + 2 * p;
        int n = n0 + r;
#pragma unroll
        for (int j = 0; j < 4; j++) { xsT[jl * 4 + j][r] = lo[j]; xsT[jl * 4 + j][r + 1] = hi[j]; }
        if (n < Nn) {
            union { __half2 h2[2]; uint2 u; } pk;
            pk.h2[0] = __floats2half2_rn(lo[0], lo[1]);
            pk.h2[1] = __floats2half2_rn(lo[2], lo[3]);
            *(uint2*)&g_h16[n * Dd + jl * 4] = pk.u;
        }
        if (n + 1 < Nn) {
            union { __half2 h2[2]; uint2 u; } pk;
            pk.h2[0] = __floats2half2_rn(hi[0], hi[1]);
            pk.h2[1] = __floats2half2_rn(hi[2], hi[3]);
            *(uint2*)&g_h16[(n + 1) * Dd + jl * 4] = pk.u;
        }
    }
#pragma unroll
    for (int it = 0; it < 2; it++) {
        int idx = tid + it * 128;
        int r = idx >> 3, c4 = (idx & 7) * 4;
        float4 v = *(const float4*)&g_Aall[r * 32 + c4];
        wsT[c4 + 0][r] = v.x;
        wsT[c4 + 1][r] = v.y;
        wsT[c4 + 2][r] = v.z;
        wsT[c4 + 3][r] = v.w;
    }
    __syncthreads();
    unsigned long long sacc[4][4];
#pragma unroll
    for (int p = 0; p < 4; p++)
#pragma unroll
        for (int j = 0; j < 4; j++) sacc[p][j] = 0ull;
#pragma unroll
    for (int kk = 0; kk < 32; kk++) {
        float4 wv = *(const float4*)&wsT[kk][jl * 4];
        unsigned long long wp[4];
        PACK2(wp[0], wv.x, wv.x);
        PACK2(wp[1], wv.y, wv.y);
        PACK2(wp[2], wv.z, wv.z);
        PACK2(wp[3], wv.w, wv.w);
#pragma unroll
        for (int p = 0; p < 4; p++) {
            unsigned long long zp = *(const unsigned long long*)&xsT[kk][g * 8 + 2 * p];
#pragma unroll
            for (int j = 0; j < 4; j++) FMA2(sacc[p][j], zp, wp[j]);
        }
    }
#pragma unroll
    for (int p = 0; p < 4; p++) {
        float lo[4], hi[4];
#pragma unroll
        for (int j = 0; j < 4; j++) UNPACK2(lo[j], hi[j], sacc[p][j]);
        int n = n0 + g * 8 + 2 * p;
        if (n < Nn) *(float4*)&g_s[n * 32 + jl * 4] = make_float4(lo[0], lo[1], lo[2], lo[3]);
        if (n + 1 < Nn) *(float4*)&g_s[(n + 1) * 32 + jl * 4] = make_float4(hi[0], hi[1], hi[2], hi[3]);
    }
}

// ---------------- CSR build ----------------
__global__ void k_hist(const int* __restrict__ ei1, int E1,
                       const int* __restrict__ ei2, int E2) {
    int e = blockIdx.x * blockDim.x + threadIdx.x;
    if (e < E1) atomicAdd(&g_deg[ei1[E1 + e]], 1);
    if (e < E2) atomicAdd(&g_deg[Nn + ei2[E2 + e]], 1);
}

__global__ __launch_bounds__(1024) void k_scan1() {
    const int set = blockIdx.y;
    const int blk = blockIdx.x;
    const int t = threadIdx.x;
    const int lane = t & 31, wid = t >> 5;
    __shared__ int wsum[32];
    const int* deg = &g_deg[set * Nn];
    int* rp = &g_rowptr[set * (Nn + 1)];
    int base = blk * TILE + t * 4;

    int4 v = make_int4(0, 0, 0, 0);
    if (base + 3 < Nn) v = *(const int4*)&deg[base];
    else {
        if (base + 0 < Nn) v.x = deg[base + 0];
        if (base + 1 < Nn) v.y = deg[base + 1];
        if (base + 2 < Nn) v.z = deg[base + 2];
        if (base + 3 < Nn) v.w = deg[base + 3];
    }
    int tsum = v.x + v.y + v.z + v.w;
    int incl = tsum;
#pragma unroll
    for (int off = 1; off < 32; off <<= 1) {
        int nv = __shfl_up_sync(0xffffffffu, incl, off);
        if (lane >= off) incl += nv;
    }
    if (lane == 31) wsum[wid] = incl;
    __syncthreads();
    if (wid == 0) {
        int w = wsum[lane];
        int wi = w;
#pragma unroll
        for (int off = 1; off < 32; off <<= 1) {
            int nv = __shfl_up_sync(0xffffffffu, wi, off);
            if (lane >= off) wi += nv;
        }
        wsum[lane] = wi - w;
        if (lane == 31) g_bsum[set * NB + blk] = wi;
    }
    __syncthreads();
    int off0 = wsum[wid] + incl - tsum;
    if (base < Nn) {
        int o = off0;
        rp[base] = o; o += v.x;
        if (base + 1 < Nn) rp[base + 1] = o; o += v.y;
        if (base + 2 < Nn) rp[base + 2] = o; o += v.z;
        if (base + 3 < Nn) rp[base + 3] = o;
    }
}

__global__ __launch_bounds__(256) void k_scan3(int E1, int E2) {
    __shared__ int boff[2 * 32];
    int t = threadIdx.x;
    if (t < 64) {
        int set = t >> 5, lane = t & 31;
        int v = (lane < NB) ? g_bsum[set * NB + lane] : 0;
        int incl = v;
#pragma unroll
        for (int off = 1; off < 32; off <<= 1) {
            int nv = __shfl_up_sync(0xffffffffu, incl, off);
            if (lane >= off) incl += nv;
        }
        boff[set * 32 + lane] = incl - v;
    }
    __syncthreads();
    int i = blockIdx.x * blockDim.x + t;
    if (i < 2 * Nn) {
        int set = (i >= Nn) ? 1 : 0;
        int loc = i - set * Nn;
        int vabs = g_rowptr[set * (Nn + 1) + loc] + boff[set * 32 + loc / TILE];
        g_rowptr[set * (Nn + 1) + loc] = vabs;
        g_cur[i] = vabs;
    }
    if (i == 0) {
        g_rowptr[Nn] = E1;
        g_rowptr[(Nn + 1) + Nn] = E2;
    }
}

__global__ void k_scatter(const int* __restrict__ ei1, int E1,
                          const int* __restrict__ ei2, int E2) {
    int e = blockIdx.x * blockDim.x + threadIdx.x;
    if (e < E1) {
        int src = ei1[e], dst = ei1[E1 + e];
        int pos = atomicAdd(&g_cur[dst], 1);
        g_csr[pos] = src;
    }
    if (e < E2) {
        int src = ei2[e], dst = ei2[E2 + e];
        int pos = atomicAdd(&g_cur[Nn + dst], 1);
        g_csr[EMAX + pos] = src;
    }
}

// ---------------- GAT layer: warp/node, lane = (head, dim-octet) -----------
__global__ __launch_bounds__(256) void k_gat(int set) {
    const int lane = threadIdx.x & 31;
    const int node = (blockIdx.x * blockDim.x + threadIdx.x) >> 5;
    if (node >= Nn) return;
    __half* Z16 = &g_Z16[(size_t)set * Nn * Cc];
    const int offd = set * 16, offs = set * 16 + 8;
    const int* csr = &g_csr[set * EMAX];
    const int beg = g_rowptr[set * (Nn + 1) + node];
    const int end = g_rowptr[set * (Nn + 1) + node + 1];

    const int head = lane >> 2;         // 0..7
    const int dpart = (lane & 3) * 8;   // dim octet base
    const bool sc_lane = (lane < 8);
    float sd = sc_lane ? g_s[node * 32 + offd + lane] : 0.f;

    float lsum = 0.f;
    unsigned long long acc[4];          // 8 f32 dims as 4 packed pairs
#pragma unroll
    for (int i = 0; i < 4; i++) acc[i] = 0ull;

    for (int e = beg; e < end; e++) {
        int src = csr[e];
        float p = 0.f;
        if (sc_lane) {
            float sc = sd + g_s[src * 32 + offs + lane];
            sc = sc > 0.f ? sc : NEG_SLOPE * sc;
            p = __expf(sc);
            lsum += p;
        }
        float ph = __shfl_sync(0xffffffffu, p, head);
        uint4 hv = *(const uint4*)&g_h16[src * Dd + dpart];
        const __half2* h2 = (const __half2*)&hv;
        unsigned long long pp;
        PACK2(pp, ph, ph);
#pragma unroll
        for (int i = 0; i < 4; i++) {
            float2 f = __half22float2(h2[i]);
            unsigned long long hp;
            PACK2(hp, f.x, f.y);
            FMA2(acc[i], hp, pp);
        }
    }
    float ls = __shfl_sync(0xffffffffu, lsum, head);
    float inv = 1.0f / ls;
    union { __half2 h2[4]; uint4 u; } outp;
#pragma unroll
    for (int i = 0; i < 4; i++) {
        float lo, hi;
        UNPACK2(lo, hi, acc[i]);
        lo *= inv; hi *= inv;
        lo = lo > 0.f ? lo : expm1f(lo);
        hi = hi > 0.f ? hi : expm1f(hi);
        outp.h2[i] = __floats2half2_rn(lo, hi);
    }
    *(uint4*)&Z16[node * Cc + head * Dd + dpart] = outp.u;
}

// ---------------- semantic score via f16 mma, 128-node M-tile ---------------
// Block: 128 nodes x 128 j, 256 threads = 4(M) x 2(N) warps.
// Warp: 2 m16 tiles x 8 n8 tiles.
__global__ __launch_bounds__(256) void k_score(const float* __restrict__ fcb,
                                               const float* __restrict__ q,
                                               int layer) {
    __shared__ __align__(16) __half Ash[128][72];
    __shared__ __align__(16) __half Bsh[128][72];
    __shared__ float sb[128], sq[128];
    __shared__ float red[256];
    const __half* __restrict__ Z16 = &g_Z16[(size_t)layer * Nn * Cc];
    const int tid = threadIdx.x;
    const int lane = tid & 31, wid = tid >> 5;
    const int wm = wid & 3, wn = wid >> 2;
    const int n0 = blockIdx.x * 128;

    if (tid < 128) { sb[tid] = fcb[tid]; sq[tid] = q[tid]; }

    float c[2][8][4];
#pragma unroll
    for (int mt2 = 0; mt2 < 2; mt2++)
#pragma unroll
        for (int nt = 0; nt < 8; nt++)
#pragma unroll
            for (int i = 0; i < 4; i++) c[mt2][nt][i] = 0.f;

    const int mt = lane >> 3, rr = lane & 7;

    for (int k0 = 0; k0 < Cc; k0 += 64) {
        // stage A: 128 rows x 64 f16
#pragma unroll
        for (int it = 0; it < 4; it++) {
            int idx = tid + it * 256;
            int row = idx >> 3, c8 = idx & 7;
            int n = n0 + row;
            int4 v = make_int4(0, 0, 0, 0);
            if (n < Nn) v = *(const int4*)&Z16[(size_t)n * Cc + k0 + c8 * 8];
            *(int4*)&Ash[row][c8 * 8] = v;
        }
        // stage B: 128 rows x 64 f16
#pragma unroll
        for (int it = 0; it < 4; it++) {
            int idx = tid + it * 256;
            int row = idx >> 3, c8 = idx & 7;
            *(int4*)&Bsh[row][c8 * 8] = *(const int4*)&g_fcw16[row * Cc + k0 + c8 * 8];
        }
        __syncthreads();
#pragma unroll
        for (int ks = 0; ks < 4; ks++) {
            const int kk = ks * 16;
            unsigned a0[2], a1[2], a2[2], a3[2];
#pragma unroll
            for (int mt2 = 0; mt2 < 2; mt2++) {
                unsigned addr = smem_u32(&Ash[wm * 32 + mt2 * 16 + ((mt & 1) << 3) + rr][kk + ((mt >> 1) << 3)]);
                LDSM4(a0[mt2], a1[mt2], a2[mt2], a3[mt2], addr);
            }
#pragma unroll
            for (int pb = 0; pb < 4; pb++) {
                unsigned b0, b1, b2, b3;
                unsigned addr = smem_u32(&Bsh[wn * 64 + pb * 16 + ((mt >> 1) << 3) + rr][kk + ((mt & 1) << 3)]);
                LDSM4(b0, b1, b2, b3, addr);
#pragma unroll
                for (int mt2 = 0; mt2 < 2; mt2++) {
                    MMA16816(c[mt2][2 * pb],     a0[mt2], a1[mt2], a2[mt2], a3[mt2], b0, b1);
                    MMA16816(c[mt2][2 * pb + 1], a0[mt2], a1[mt2], a2[mt2], a3[mt2], b2, b3);
                }
            }
        }
        __syncthreads();
    }

    float psum = 0.f;
    const int rbase = lane >> 2, cb = (lane & 3) * 2;
#pragma unroll
    for (int mt2 = 0; mt2 < 2; mt2++) {
#pragma unroll
        for (int nt = 0; nt < 8; nt++) {
#pragma unroll
            for (int i = 0; i < 4; i++) {
                int m = wm * 32 + mt2 * 16 + rbase + ((i >> 1) << 3);
                int j = wn * 64 + nt * 8 + cb + (i & 1);
                if (n0 + m < Nn) psum += tanh_apx(c[mt2][nt][i] + sb[j]) * sq[j];
            }
        }
    }
    red[tid] = psum;
    __syncthreads();
    for (int s = 128; s > 0; s >>= 1) {
        if (tid < s) red[tid] += red[tid + s];
        __syncthreads();
    }
    if (tid == 0) atomicAdd(&g_t[layer], red[0]);
}

// ---------------- out = V0*Z1 + V1*Z2 (softmax inline; f16 in, f32 out) -----
__global__ __launch_bounds__(256) void k_comb(float* __restrict__ out) {
    int i = blockIdx.x * blockDim.x + threadIdx.x;
    const int total8 = Nn * Cc / 8;
    if (i >= total8) return;
    float s0 = g_t[0] * (1.0f / (float)Nn);
    float s1 = g_t[1] * (1.0f / (float)Nn);
    float mm = fmaxf(s0, s1);
    float e0 = __expf(s0 - mm), e1 = __expf(s1 - mm);
    float inv = 1.0f / (e0 + e1);
    float v0 = e0 * inv, v1 = e1 * inv;
    uint4 ra = *(const uint4*)&g_Z16[(size_t)i * 8];
    uint4 rb = *(const uint4*)&g_Z16[(size_t)Nn * Cc + (size_t)i * 8];
    const __half2* ha = (const __half2*)&ra;
    const __half2* hb = (const __half2*)&rb;
    float4 o0, o1;
    float2 a, b;
    a = __half22float2(ha[0]); b = __half22float2(hb[0]);
    o0.x = v0 * a.x + v1 * b.x; o0.y = v0 * a.y + v1 * b.y;
    a = __half22float2(ha[1]); b = __half22float2(hb[1]);
    o0.z = v0 * a.x + v1 * b.x; o0.w = v0 * a.y + v1 * b.y;
    a = __half22float2(ha[2]); b = __half22float2(hb[2]);
    o1.x = v0 * a.x + v1 * b.x; o1.y = v0 * a.y + v1 * b.y;
    a = __half22float2(ha[3]); b = __half22float2(hb[3]);
    o1.z = v0 * a.x + v1 * b.x; o1.w = v0 * a.y + v1 * b.y;
    *(float4*)&out[(size_t)i * 8] = o0;
    *(float4*)&out[(size_t)i * 8 + 4] = o1;
}

// ---------------- launch (multi-stream fork/join, capture-safe) -------------
extern "C" void kernel_launch(void* const* d_in, const int* in_sizes, int n_in,
                              void* d_out, int out_size) {
    const float* x    = (const float*)d_in[0];
    const float* W    = (const float*)d_in[1];
    const float* att1 = (const float*)d_in[2];
    const float* att2 = (const float*)d_in[3];
    const float* fcw  = (const float*)d_in[4];
    const float* fcb  = (const float*)d_in[5];
    const float* q    = (const float*)d_in[6];
    const int*   ei1  = (const int*)d_in[7];
    const int*   ei2  = (const int*)d_in[8];
    const int E1 = in_sizes[7] / 2;
    const int E2 = in_sizes[8] / 2;
    const int Emax = (E1 > E2) ? E1 : E2;
    float* out = (float*)d_out;

    static cudaStream_t s1 = 0;
    static cudaEvent_t evSetup = 0, evCsr = 0, evHs = 0, evB = 0;
    if (!s1) {
        cudaStreamCreateWithFlags(&s1, cudaStreamNonBlocking);
        cudaEventCreateWithFlags(&evSetup, cudaEventDisableTiming);
        cudaEventCreateWithFlags(&evCsr, cudaEventDisableTiming);
        cudaEventCreateWithFlags(&evHs, cudaEventDisableTiming);
        cudaEventCreateWithFlags(&evB, cudaEventDisableTiming);
    }

    // main stream: setup, then fork
    k_setup<<<(2 * Nn + 1023) / 1024, 1024>>>(att1, att2, fcw);
    cudaEventRecord(evSetup, 0);

    // side stream: CSR build chain (independent of k_hs)
    cudaStreamWaitEvent(s1, evSetup, 0);
    k_hist<<<(Emax + 255) / 256, 256, 0, s1>>>(ei1, E1, ei2, E2);
    k_scan1<<<dim3(NB, 2), 1024, 0, s1>>>();
    k_scan3<<<(2 * Nn + 255) / 256, 256, 0, s1>>>(E1, E2);
    k_scatter<<<(Emax + 255) / 256, 256, 0, s1>>>(ei1, E1, ei2, E2);
    cudaEventRecord(evCsr, s1);

    // main stream: the h/s GEMM (overlaps the CSR chain)
    k_hs<<<(Nn + 127) / 128, 128>>>(x, W);
    cudaEventRecord(evHs, 0);

    // layer 0 pipeline on main stream
    cudaStreamWaitEvent(0, evCsr, 0);
    k_gat<<<(Nn + 7) / 8, 256>>>(0);
    k_score<<<(Nn + 127) / 128, 256>>>(fcb, q, 0);

    // layer 1 pipeline on side stream
    cudaStreamWaitEvent(s1, evHs, 0);
    k_gat<<<(Nn + 7) / 8, 256, 0, s1>>>(1);
    k_score<<<(Nn + 127) / 128, 256, 0, s1>>>(fcb, q, 1);
    cudaEventRecord(evB, s1);

    // join, then final combine (softmax inline)
    cudaStreamWaitEvent(0, evB, 0);
    k_comb<<<(Nn * Cc / 8 + 255) / 256, 256>>>(out);
}